// round 7
// baseline (speedup 1.0000x reference)
#include <cuda_runtime.h>
#include <cstdint>

// Problem constants
#define B_   8
#define N1_  8192
#define N2_  2048
#define K_   8
#define C1_  64
#define C2_  128
#define H_   128
#define CAT_ 192   // H + C1

// Device-global scratch (allocation-free)
__device__ int   g_knn[B_ * N1_ * K_];                 // 2 MB
__device__ float g_P[B_ * N2_ * H_];                   // 8 MB: feat2 @ W0[:128] + b0
__device__ float g_cat[B_ * N1_ * CAT_];               // 50 MB: [pooled | feat1]

// ---------------------------------------------------------------------------
// f32x2 helpers
// ---------------------------------------------------------------------------
__device__ __forceinline__ unsigned long long ffma2(unsigned long long a,
                                                    unsigned long long b,
                                                    unsigned long long c) {
    unsigned long long d;
    asm("fma.rn.f32x2 %0, %1, %2, %3;" : "=l"(d) : "l"(a), "l"(b), "l"(c));
    return d;
}
__device__ __forceinline__ unsigned long long dup2(float v) {
    unsigned long long u;
    asm("mov.b64 %0, {%1, %1};" : "=l"(u) : "f"(v));
    return u;
}
__device__ __forceinline__ unsigned long long pack2(float x, float y) {
    unsigned long long u;  // lo = x, hi = y
    asm("mov.b64 %0, {%1, %2};" : "=l"(u) : "f"(x), "f"(y));
    return u;
}
__device__ __forceinline__ float2 u2f(unsigned long long u) {
    float2 v;
    asm("mov.b64 {%0, %1}, %2;" : "=f"(v.x), "=f"(v.y) : "l"(u));
    return v;
}

// ---------------------------------------------------------------------------
// Kernel 1: brute-force KNN (unchanged from passing R4 version)
// ---------------------------------------------------------------------------
__global__ __launch_bounds__(256) void knn_kernel(
    const float* __restrict__ xyz1,
    const float* __restrict__ xyz2) {
    __shared__ float sx[N2_], sy[N2_], sz[N2_];

    const int b = blockIdx.y;
    const int n = blockIdx.x * 256 + threadIdx.x;

    const float* p2 = xyz2 + (size_t)b * N2_ * 3;
    for (int j = threadIdx.x; j < N2_; j += 256) {
        sx[j] = p2[3 * j + 0];
        sy[j] = p2[3 * j + 1];
        sz[j] = p2[3 * j + 2];
    }
    __syncthreads();

    const int g = b * N1_ + n;
    const float qx = xyz1[3 * (size_t)g + 0];
    const float qy = xyz1[3 * (size_t)g + 1];
    const float qz = xyz1[3 * (size_t)g + 2];

    float bd[K_];
    int   bi[K_];
#pragma unroll
    for (int i = 0; i < K_; ++i) { bd[i] = 3.4e38f; bi[i] = 0; }

    for (int j = 0; j < N2_; ++j) {
        const float dx = sx[j] - qx;
        const float dy = sy[j] - qy;
        const float dz = sz[j] - qz;
        const float d = fmaf(dx, dx, fmaf(dy, dy, dz * dz));
        if (d < bd[K_ - 1]) {
            bd[K_ - 1] = d; bi[K_ - 1] = j;
#pragma unroll
            for (int s = K_ - 1; s > 0; --s) {
                if (bd[s] < bd[s - 1]) {
                    const float td = bd[s]; bd[s] = bd[s - 1]; bd[s - 1] = td;
                    const int   ti = bi[s]; bi[s] = bi[s - 1]; bi[s - 1] = ti;
                }
            }
        }
    }
#pragma unroll
    for (int i = 0; i < K_; ++i) g_knn[(size_t)g * K_ + i] = bi[i];
}

// ---------------------------------------------------------------------------
// Kernel 2: P = feat2 @ W0[:128,:] + b0   (gather-invariant GEMM1 part)
// Block = 128 threads, 8 feat2 rows. Thread t = output column; 4 row-pair
// accumulators; activations broadcast from smem as adjacent row pairs.
// ---------------------------------------------------------------------------
__global__ __launch_bounds__(128) void precompute_p_kernel(
    const float* __restrict__ feat2,
    const float* __restrict__ W0,
    const float* __restrict__ b0) {
    __shared__ float s_f[C2_ * 10];  // [k][10] (8 rows + pad, 8B-aligned pairs)

    const int t = threadIdx.x;
    const int base = blockIdx.x * 8;  // row in [0, B*N2)

    for (int idx = t; idx < 8 * C2_; idx += 128) {
        const int r = idx >> 7, k = idx & 127;
        s_f[k * 10 + r] = feat2[(size_t)(base + r) * C2_ + k];
    }
    __syncthreads();

    unsigned long long acc[4];
    const unsigned long long bb = dup2(b0[t]);
#pragma unroll
    for (int rp = 0; rp < 4; ++rp) acc[rp] = bb;

#pragma unroll 4
    for (int k = 0; k < C2_; ++k) {
        const unsigned long long wd = dup2(W0[k * H_ + t]);
#pragma unroll
        for (int rp = 0; rp < 4; ++rp) {
            const unsigned long long a =
                *(const unsigned long long*)&s_f[k * 10 + 2 * rp];
            acc[rp] = ffma2(a, wd, acc[rp]);
        }
    }
#pragma unroll
    for (int rp = 0; rp < 4; ++rp) {
        const float2 v = u2f(acc[rp]);
        g_P[(size_t)(base + 2 * rp) * H_ + t]     = v.x;
        g_P[(size_t)(base + 2 * rp + 1) * H_ + t] = v.y;
    }
}

// ---------------------------------------------------------------------------
// Kernel 3: fused gather+xyz MLP1-finish + GEMM2 + relu + maxpool + concat.
// One warp per query point, 8 points per 256-thread block.
// GEMM2 inner loop per k per warp: 2 LDS.128 + 4 LDG.32 + 4 dup + 16 FFMA2
//  -> ~6 L1 wavefronts per 32 FMA-pipe cycles (FMA-bound by design).
// ---------------------------------------------------------------------------
__global__ __launch_bounds__(256) void fused_kernel(
    const float* __restrict__ xyz1,
    const float* __restrict__ xyz2,
    const float* __restrict__ feat1,
    const float* __restrict__ W0,
    const float* __restrict__ W1,
    const float* __restrict__ b1) {
    __shared__ unsigned long long h_s[8][H_][4];  // [warp][k][row-pair]

    const int w    = threadIdx.x >> 5;
    const int lane = threadIdx.x & 31;
    const int g    = blockIdx.x * 8 + w;
    const int b    = g >> 13;  // N1 = 8192

    // ---- finish GEMM1: h = relu(P[j] + xyz_diff @ W0[128:131,:]) ----
    {
        const int rp = lane & 3, cg = lane >> 2;
        const int r0 = 2 * rp, r1 = r0 + 1;
        const int j0 = g_knn[(size_t)g * K_ + r0];
        const int j1 = g_knn[(size_t)g * K_ + r1];
        const float qx = xyz1[(size_t)g * 3 + 0];
        const float qy = xyz1[(size_t)g * 3 + 1];
        const float qz = xyz1[(size_t)g * 3 + 2];
        const float* p0 = xyz2 + (size_t)(b * N2_ + j0) * 3;
        const float* p1 = xyz2 + (size_t)(b * N2_ + j1) * 3;
        const float d00 = p0[0] - qx, d01 = p0[1] - qy, d02 = p0[2] - qz;
        const float d10 = p1[0] - qx, d11 = p1[1] - qy, d12 = p1[2] - qz;
        const float* P0 = g_P + (size_t)(b * N2_ + j0) * H_;
        const float* P1 = g_P + (size_t)(b * N2_ + j1) * H_;
#pragma unroll
        for (int i = 0; i < 16; ++i) {
            const int c = cg + 8 * i;
            const float v0 = W0[128 * H_ + c];
            const float v1 = W0[129 * H_ + c];
            const float v2 = W0[130 * H_ + c];
            float h0 = __ldcs(P0 + c);
            float h1 = __ldcs(P1 + c);
            h0 = fmaf(d02, v2, fmaf(d01, v1, fmaf(d00, v0, h0)));
            h1 = fmaf(d12, v2, fmaf(d11, v1, fmaf(d10, v0, h1)));
            h_s[w][c][rp] = pack2(fmaxf(h0, 0.0f), fmaxf(h1, 0.0f));
        }
    }
    __syncwarp();

    // ---- GEMM2: (8 x 128) @ (128 x 128); rows packed in f32x2 pairs ----
    unsigned long long acc[4][4];  // [row-pair][col i], col = lane + 32*i
#pragma unroll
    for (int i = 0; i < 4; ++i) {
        const unsigned long long bb = dup2(b1[lane + 32 * i]);
#pragma unroll
        for (int r = 0; r < 4; ++r) acc[r][i] = bb;
    }
#pragma unroll 2
    for (int k = 0; k < H_; ++k) {
        const ulonglong2 hv01 = *(const ulonglong2*)&h_s[w][k][0];
        const ulonglong2 hv23 = *(const ulonglong2*)&h_s[w][k][2];
        const unsigned long long hv[4] = {hv01.x, hv01.y, hv23.x, hv23.y};
#pragma unroll
        for (int i = 0; i < 4; ++i) {
            const unsigned long long wd = dup2(W1[k * H_ + lane + 32 * i]);
#pragma unroll
            for (int r = 0; r < 4; ++r) acc[r][i] = ffma2(hv[r], wd, acc[r][i]);
        }
    }

    // ---- relu + maxpool over 8 neighbors; write [pooled | feat1] ----
    float* catg = g_cat + (size_t)g * CAT_;
#pragma unroll
    for (int i = 0; i < 4; ++i) {
        float m = 0.0f;  // max_r relu(x) == max(0, max_r x)
#pragma unroll
        for (int r = 0; r < 4; ++r) {
            const float2 v = u2f(acc[r][i]);
            m = fmaxf(m, fmaxf(v.x, v.y));
        }
        catg[lane + 32 * i] = m;
    }
    catg[H_ + lane]      = feat1[(size_t)g * C1_ + lane];
    catg[H_ + 32 + lane] = feat1[(size_t)g * C1_ + 32 + lane];
}

// ---------------------------------------------------------------------------
// Kernel 4: GEMM3  out = relu(cat @ W2 + b2), cat = (BN1 x 192).
// Block = 256 threads, 32 points. Thread: 4 points (2 row-pairs) x 4 cols.
// ---------------------------------------------------------------------------
__global__ __launch_bounds__(256) void gemm3_kernel(
    const float* __restrict__ W2,
    const float* __restrict__ b2,
    float* __restrict__ out) {
    __shared__ float cat_s[CAT_ * 34];  // [k][34]: 32 points + pad (136B rows)

    const int t = threadIdx.x;
    const int base = blockIdx.x * 32;

    for (int idx = t; idx < 32 * CAT_; idx += 256) {
        const int p = idx / CAT_;
        const int k = idx - p * CAT_;
        cat_s[k * 34 + p] = __ldcs(&g_cat[(size_t)(base + p) * CAT_ + k]);
    }
    __syncthreads();

    const int q  = t & 7;   // point-quad: points 4q .. 4q+3
    const int cg = t >> 3;  // cols: cg + 32*i

    unsigned long long acc[2][4];
#pragma unroll
    for (int i = 0; i < 4; ++i) {
        const unsigned long long bb = dup2(b2[cg + 32 * i]);
        acc[0][i] = bb;
        acc[1][i] = bb;
    }

#pragma unroll 2
    for (int k = 0; k < CAT_; ++k) {
        const unsigned long long a0 =
            *(const unsigned long long*)&cat_s[k * 34 + 4 * q];
        const unsigned long long a1 =
            *(const unsigned long long*)&cat_s[k * 34 + 4 * q + 2];
#pragma unroll
        for (int i = 0; i < 4; ++i) {
            const unsigned long long wd = dup2(W2[k * H_ + cg + 32 * i]);
            acc[0][i] = ffma2(a0, wd, acc[0][i]);
            acc[1][i] = ffma2(a1, wd, acc[1][i]);
        }
    }

#pragma unroll
    for (int pr = 0; pr < 2; ++pr) {
#pragma unroll
        for (int i = 0; i < 4; ++i) {
            const float2 v = u2f(acc[pr][i]);
            const int c = cg + 32 * i;
            out[(size_t)(base + 4 * q + 2 * pr)     * H_ + c] = fmaxf(v.x, 0.0f);
            out[(size_t)(base + 4 * q + 2 * pr + 1) * H_ + c] = fmaxf(v.y, 0.0f);
        }
    }
}

// ---------------------------------------------------------------------------
// Launch
// ---------------------------------------------------------------------------
extern "C" void kernel_launch(void* const* d_in, const int* in_sizes, int n_in,
                              void* d_out, int out_size) {
    const float* xyz1  = (const float*)d_in[0];
    const float* xyz2  = (const float*)d_in[1];
    const float* feat1 = (const float*)d_in[2];
    const float* feat2 = (const float*)d_in[3];
    const float* W0    = (const float*)d_in[4];
    const float* b0    = (const float*)d_in[5];
    const float* W1    = (const float*)d_in[6];
    const float* b1    = (const float*)d_in[7];
    const float* W2    = (const float*)d_in[8];
    const float* b2    = (const float*)d_in[9];
    float* out = (float*)d_out;

    precompute_p_kernel<<<(B_ * N2_) / 8, 128>>>(feat2, W0, b0);
    knn_kernel<<<dim3(N1_ / 256, B_), 256>>>(xyz1, xyz2);
    fused_kernel<<<(B_ * N1_) / 8, 256>>>(xyz1, xyz2, feat1, W0, W1, b1);
    gemm3_kernel<<<(B_ * N1_) / 32, 256>>>(W2, b2, out);
}

// round 8
// speedup vs baseline: 1.0019x; 1.0019x over previous
#include <cuda_runtime.h>
#include <cstdint>

// Problem constants
#define B_   8
#define N1_  8192
#define N2_  2048
#define K_   8
#define C1_  64
#define C2_  128
#define H_   128
#define CAT_ 192   // H + C1

// Device-global scratch (allocation-free)
__device__ int   g_knn[B_ * N1_ * K_];                 // 2 MB
__device__ float g_P[B_ * N2_ * H_];                   // 8 MB: feat2 @ W0[:128] + b0
__device__ float g_cat[B_ * N1_ * CAT_];               // 50 MB: [pooled | feat1]

// ---------------------------------------------------------------------------
// f32x2 helpers
// ---------------------------------------------------------------------------
__device__ __forceinline__ unsigned long long ffma2(unsigned long long a,
                                                    unsigned long long b,
                                                    unsigned long long c) {
    unsigned long long d;
    asm("fma.rn.f32x2 %0, %1, %2, %3;" : "=l"(d) : "l"(a), "l"(b), "l"(c));
    return d;
}
__device__ __forceinline__ unsigned long long dup2(float v) {
    unsigned long long u;
    asm("mov.b64 %0, {%1, %1};" : "=l"(u) : "f"(v));
    return u;
}
__device__ __forceinline__ unsigned long long pack2(float x, float y) {
    unsigned long long u;  // lo = x, hi = y
    asm("mov.b64 %0, {%1, %2};" : "=l"(u) : "f"(x), "f"(y));
    return u;
}
__device__ __forceinline__ float2 u2f(unsigned long long u) {
    float2 v;
    asm("mov.b64 {%0, %1}, %2;" : "=f"(v.x), "=f"(v.y) : "l"(u));
    return v;
}

// ---------------------------------------------------------------------------
// Kernel 1: brute-force KNN (unchanged from passing R4 version)
// ---------------------------------------------------------------------------
__global__ __launch_bounds__(256) void knn_kernel(
    const float* __restrict__ xyz1,
    const float* __restrict__ xyz2) {
    __shared__ float sx[N2_], sy[N2_], sz[N2_];

    const int b = blockIdx.y;
    const int n = blockIdx.x * 256 + threadIdx.x;

    const float* p2 = xyz2 + (size_t)b * N2_ * 3;
    for (int j = threadIdx.x; j < N2_; j += 256) {
        sx[j] = p2[3 * j + 0];
        sy[j] = p2[3 * j + 1];
        sz[j] = p2[3 * j + 2];
    }
    __syncthreads();

    const int g = b * N1_ + n;
    const float qx = xyz1[3 * (size_t)g + 0];
    const float qy = xyz1[3 * (size_t)g + 1];
    const float qz = xyz1[3 * (size_t)g + 2];

    float bd[K_];
    int   bi[K_];
#pragma unroll
    for (int i = 0; i < K_; ++i) { bd[i] = 3.4e38f; bi[i] = 0; }

    for (int j = 0; j < N2_; ++j) {
        const float dx = sx[j] - qx;
        const float dy = sy[j] - qy;
        const float dz = sz[j] - qz;
        const float d = fmaf(dx, dx, fmaf(dy, dy, dz * dz));
        if (d < bd[K_ - 1]) {
            bd[K_ - 1] = d; bi[K_ - 1] = j;
#pragma unroll
            for (int s = K_ - 1; s > 0; --s) {
                if (bd[s] < bd[s - 1]) {
                    const float td = bd[s]; bd[s] = bd[s - 1]; bd[s - 1] = td;
                    const int   ti = bi[s]; bi[s] = bi[s - 1]; bi[s - 1] = ti;
                }
            }
        }
    }
#pragma unroll
    for (int i = 0; i < K_; ++i) g_knn[(size_t)g * K_ + i] = bi[i];
}

// ---------------------------------------------------------------------------
// Kernel 2: P = feat2 @ W0[:128,:] + b0   (gather-invariant GEMM1 part)
// Block = 128 threads, 8 feat2 rows. Thread t = output column; 4 row-pair
// accumulators; activations broadcast from smem as adjacent row pairs.
// ---------------------------------------------------------------------------
__global__ __launch_bounds__(128) void precompute_p_kernel(
    const float* __restrict__ feat2,
    const float* __restrict__ W0,
    const float* __restrict__ b0) {
    __shared__ float s_f[C2_ * 10];  // [k][10] (8 rows + pad, 8B-aligned pairs)

    const int t = threadIdx.x;
    const int base = blockIdx.x * 8;  // row in [0, B*N2)

    for (int idx = t; idx < 8 * C2_; idx += 128) {
        const int r = idx >> 7, k = idx & 127;
        s_f[k * 10 + r] = feat2[(size_t)(base + r) * C2_ + k];
    }
    __syncthreads();

    unsigned long long acc[4];
    const unsigned long long bb = dup2(b0[t]);
#pragma unroll
    for (int rp = 0; rp < 4; ++rp) acc[rp] = bb;

#pragma unroll 4
    for (int k = 0; k < C2_; ++k) {
        const unsigned long long wd = dup2(W0[k * H_ + t]);
#pragma unroll
        for (int rp = 0; rp < 4; ++rp) {
            const unsigned long long a =
                *(const unsigned long long*)&s_f[k * 10 + 2 * rp];
            acc[rp] = ffma2(a, wd, acc[rp]);
        }
    }
#pragma unroll
    for (int rp = 0; rp < 4; ++rp) {
        const float2 v = u2f(acc[rp]);
        g_P[(size_t)(base + 2 * rp) * H_ + t]     = v.x;
        g_P[(size_t)(base + 2 * rp + 1) * H_ + t] = v.y;
    }
}

// ---------------------------------------------------------------------------
// Kernel 3: fused gather+xyz MLP1-finish + GEMM2 + relu + maxpool + concat.
// One warp per query point, 8 points per 256-thread block.
// GEMM2 inner loop per k per warp: 2 LDS.128 + 4 LDG.32 + 4 dup + 16 FFMA2
//  -> ~6 L1 wavefronts per 32 FMA-pipe cycles (FMA-bound by design).
// ---------------------------------------------------------------------------
__global__ __launch_bounds__(256) void fused_kernel(
    const float* __restrict__ xyz1,
    const float* __restrict__ xyz2,
    const float* __restrict__ feat1,
    const float* __restrict__ W0,
    const float* __restrict__ W1,
    const float* __restrict__ b1) {
    __shared__ unsigned long long h_s[8][H_][4];  // [warp][k][row-pair]

    const int w    = threadIdx.x >> 5;
    const int lane = threadIdx.x & 31;
    const int g    = blockIdx.x * 8 + w;
    const int b    = g >> 13;  // N1 = 8192

    // ---- finish GEMM1: h = relu(P[j] + xyz_diff @ W0[128:131,:]) ----
    {
        const int rp = lane & 3, cg = lane >> 2;
        const int r0 = 2 * rp, r1 = r0 + 1;
        const int j0 = g_knn[(size_t)g * K_ + r0];
        const int j1 = g_knn[(size_t)g * K_ + r1];
        const float qx = xyz1[(size_t)g * 3 + 0];
        const float qy = xyz1[(size_t)g * 3 + 1];
        const float qz = xyz1[(size_t)g * 3 + 2];
        const float* p0 = xyz2 + (size_t)(b * N2_ + j0) * 3;
        const float* p1 = xyz2 + (size_t)(b * N2_ + j1) * 3;
        const float d00 = p0[0] - qx, d01 = p0[1] - qy, d02 = p0[2] - qz;
        const float d10 = p1[0] - qx, d11 = p1[1] - qy, d12 = p1[2] - qz;
        const float* P0 = g_P + (size_t)(b * N2_ + j0) * H_;
        const float* P1 = g_P + (size_t)(b * N2_ + j1) * H_;
#pragma unroll
        for (int i = 0; i < 16; ++i) {
            const int c = cg + 8 * i;
            const float v0 = W0[128 * H_ + c];
            const float v1 = W0[129 * H_ + c];
            const float v2 = W0[130 * H_ + c];
            float h0 = __ldcs(P0 + c);
            float h1 = __ldcs(P1 + c);
            h0 = fmaf(d02, v2, fmaf(d01, v1, fmaf(d00, v0, h0)));
            h1 = fmaf(d12, v2, fmaf(d11, v1, fmaf(d10, v0, h1)));
            h_s[w][c][rp] = pack2(fmaxf(h0, 0.0f), fmaxf(h1, 0.0f));
        }
    }
    __syncwarp();

    // ---- GEMM2: (8 x 128) @ (128 x 128); rows packed in f32x2 pairs ----
    unsigned long long acc[4][4];  // [row-pair][col i], col = lane + 32*i
#pragma unroll
    for (int i = 0; i < 4; ++i) {
        const unsigned long long bb = dup2(b1[lane + 32 * i]);
#pragma unroll
        for (int r = 0; r < 4; ++r) acc[r][i] = bb;
    }
#pragma unroll 2
    for (int k = 0; k < H_; ++k) {
        const ulonglong2 hv01 = *(const ulonglong2*)&h_s[w][k][0];
        const ulonglong2 hv23 = *(const ulonglong2*)&h_s[w][k][2];
        const unsigned long long hv[4] = {hv01.x, hv01.y, hv23.x, hv23.y};
#pragma unroll
        for (int i = 0; i < 4; ++i) {
            const unsigned long long wd = dup2(W1[k * H_ + lane + 32 * i]);
#pragma unroll
            for (int r = 0; r < 4; ++r) acc[r][i] = ffma2(hv[r], wd, acc[r][i]);
        }
    }

    // ---- relu + maxpool over 8 neighbors; write [pooled | feat1] ----
    float* catg = g_cat + (size_t)g * CAT_;
#pragma unroll
    for (int i = 0; i < 4; ++i) {
        float m = 0.0f;  // max_r relu(x) == max(0, max_r x)
#pragma unroll
        for (int r = 0; r < 4; ++r) {
            const float2 v = u2f(acc[r][i]);
            m = fmaxf(m, fmaxf(v.x, v.y));
        }
        catg[lane + 32 * i] = m;
    }
    catg[H_ + lane]      = feat1[(size_t)g * C1_ + lane];
    catg[H_ + 32 + lane] = feat1[(size_t)g * C1_ + 32 + lane];
}

// ---------------------------------------------------------------------------
// Kernel 4: GEMM3  out = relu(cat @ W2 + b2), cat = (BN1 x 192).
// Block = 256 threads, 32 points. Thread: 4 points (2 row-pairs) x 4 cols.
// ---------------------------------------------------------------------------
__global__ __launch_bounds__(256) void gemm3_kernel(
    const float* __restrict__ W2,
    const float* __restrict__ b2,
    float* __restrict__ out) {
    __shared__ float cat_s[CAT_ * 34];  // [k][34]: 32 points + pad (136B rows)

    const int t = threadIdx.x;
    const int base = blockIdx.x * 32;

    for (int idx = t; idx < 32 * CAT_; idx += 256) {
        const int p = idx / CAT_;
        const int k = idx - p * CAT_;
        cat_s[k * 34 + p] = __ldcs(&g_cat[(size_t)(base + p) * CAT_ + k]);
    }
    __syncthreads();

    const int q  = t & 7;   // point-quad: points 4q .. 4q+3
    const int cg = t >> 3;  // cols: cg + 32*i

    unsigned long long acc[2][4];
#pragma unroll
    for (int i = 0; i < 4; ++i) {
        const unsigned long long bb = dup2(b2[cg + 32 * i]);
        acc[0][i] = bb;
        acc[1][i] = bb;
    }

#pragma unroll 2
    for (int k = 0; k < CAT_; ++k) {
        const unsigned long long a0 =
            *(const unsigned long long*)&cat_s[k * 34 + 4 * q];
        const unsigned long long a1 =
            *(const unsigned long long*)&cat_s[k * 34 + 4 * q + 2];
#pragma unroll
        for (int i = 0; i < 4; ++i) {
            const unsigned long long wd = dup2(W2[k * H_ + cg + 32 * i]);
            acc[0][i] = ffma2(a0, wd, acc[0][i]);
            acc[1][i] = ffma2(a1, wd, acc[1][i]);
        }
    }

#pragma unroll
    for (int pr = 0; pr < 2; ++pr) {
#pragma unroll
        for (int i = 0; i < 4; ++i) {
            const float2 v = u2f(acc[pr][i]);
            const int c = cg + 32 * i;
            out[(size_t)(base + 4 * q + 2 * pr)     * H_ + c] = fmaxf(v.x, 0.0f);
            out[(size_t)(base + 4 * q + 2 * pr + 1) * H_ + c] = fmaxf(v.y, 0.0f);
        }
    }
}

// ---------------------------------------------------------------------------
// Launch
// ---------------------------------------------------------------------------
extern "C" void kernel_launch(void* const* d_in, const int* in_sizes, int n_in,
                              void* d_out, int out_size) {
    const float* xyz1  = (const float*)d_in[0];
    const float* xyz2  = (const float*)d_in[1];
    const float* feat1 = (const float*)d_in[2];
    const float* feat2 = (const float*)d_in[3];
    const float* W0    = (const float*)d_in[4];
    const float* b0    = (const float*)d_in[5];
    const float* W1    = (const float*)d_in[6];
    const float* b1    = (const float*)d_in[7];
    const float* W2    = (const float*)d_in[8];
    const float* b2    = (const float*)d_in[9];
    float* out = (float*)d_out;

    precompute_p_kernel<<<(B_ * N2_) / 8, 128>>>(feat2, W0, b0);
    knn_kernel<<<dim3(N1_ / 256, B_), 256>>>(xyz1, xyz2);
    fused_kernel<<<(B_ * N1_) / 8, 256>>>(xyz1, xyz2, feat1, W0, W1, b1);
    gemm3_kernel<<<(B_ * N1_) / 32, 256>>>(W2, b2, out);
}

// round 9
// speedup vs baseline: 1.0731x; 1.0711x over previous
#include <cuda_runtime.h>
#include <cstdint>

// Problem constants
#define B_   8
#define N1_  8192
#define N2_  2048
#define K_   8
#define C1_  64
#define C2_  128
#define H_   128
#define CAT_ 192   // H + C1

// Device-global scratch (allocation-free)
__device__ int   g_knn[B_ * N1_ * K_];     // 2 MB
__device__ float g_P[B_ * N2_ * H_];       // 8 MB: feat2 @ W0[:128] + b0
__device__ float g_pool[B_ * N1_ * H_];    // 33 MB: maxpooled hidden

// ---------------------------------------------------------------------------
// f32x2 helpers
// ---------------------------------------------------------------------------
__device__ __forceinline__ unsigned long long ffma2(unsigned long long a,
                                                    unsigned long long b,
                                                    unsigned long long c) {
    unsigned long long d;
    asm("fma.rn.f32x2 %0, %1, %2, %3;" : "=l"(d) : "l"(a), "l"(b), "l"(c));
    return d;
}
__device__ __forceinline__ unsigned long long dup2(float v) {
    unsigned long long u;
    asm("mov.b64 %0, {%1, %1};" : "=l"(u) : "f"(v));
    return u;
}
__device__ __forceinline__ unsigned long long pack2(float x, float y) {
    unsigned long long u;  // lo = x, hi = y
    asm("mov.b64 %0, {%1, %2};" : "=l"(u) : "f"(x), "f"(y));
    return u;
}
__device__ __forceinline__ float2 u2f(unsigned long long u) {
    float2 v;
    asm("mov.b64 {%0, %1}, %2;" : "=f"(v.x), "=f"(v.y) : "l"(u));
    return v;
}

// ---------------------------------------------------------------------------
// Kernel 1: brute-force KNN.
// Ranking key: ||p||^2 - 2 p.q  (order-identical to ||p-q||^2; the ||q||^2
// term is constant per query). ||p||^2 precomputed into float4.w.
// Inner loop: 1 broadcast LDS.128 + 3 FMA + compare.
// ---------------------------------------------------------------------------
__global__ __launch_bounds__(256) void knn_kernel(
    const float* __restrict__ xyz1,
    const float* __restrict__ xyz2) {
    __shared__ float4 sp[N2_];

    const int b = blockIdx.y;
    const int n = blockIdx.x * 256 + threadIdx.x;

    const float* p2 = xyz2 + (size_t)b * N2_ * 3;
    for (int j = threadIdx.x; j < N2_; j += 256) {
        const float x = p2[3 * j + 0];
        const float y = p2[3 * j + 1];
        const float z = p2[3 * j + 2];
        sp[j] = make_float4(x, y, z, fmaf(x, x, fmaf(y, y, z * z)));
    }
    __syncthreads();

    const int g = b * N1_ + n;
    const float mx = -2.0f * xyz1[3 * (size_t)g + 0];
    const float my = -2.0f * xyz1[3 * (size_t)g + 1];
    const float mz = -2.0f * xyz1[3 * (size_t)g + 2];

    float bd[K_];
    int   bi[K_];
#pragma unroll
    for (int i = 0; i < K_; ++i) { bd[i] = 3.4e38f; bi[i] = 0; }

#pragma unroll 4
    for (int j = 0; j < N2_; ++j) {
        const float4 p = sp[j];
        const float key = fmaf(p.x, mx, fmaf(p.y, my, fmaf(p.z, mz, p.w)));
        if (key < bd[K_ - 1]) {
            bd[K_ - 1] = key; bi[K_ - 1] = j;
#pragma unroll
            for (int s = K_ - 1; s > 0; --s) {
                if (bd[s] < bd[s - 1]) {
                    const float td = bd[s]; bd[s] = bd[s - 1]; bd[s - 1] = td;
                    const int   ti = bi[s]; bi[s] = bi[s - 1]; bi[s - 1] = ti;
                }
            }
        }
    }

#pragma unroll
    for (int i = 0; i < K_; ++i) g_knn[(size_t)g * K_ + i] = bi[i];
}

// ---------------------------------------------------------------------------
// Kernel 2: P = feat2 @ W0[:128,:] + b0   (gather-invariant GEMM1 part)
// ---------------------------------------------------------------------------
__global__ __launch_bounds__(128) void precompute_p_kernel(
    const float* __restrict__ feat2,
    const float* __restrict__ W0,
    const float* __restrict__ b0) {
    __shared__ float s_f[C2_ * 10];  // [k][10] (8 rows + pad)

    const int t = threadIdx.x;
    const int base = blockIdx.x * 8;

    for (int idx = t; idx < 8 * C2_; idx += 128) {
        const int r = idx >> 7, k = idx & 127;
        s_f[k * 10 + r] = feat2[(size_t)(base + r) * C2_ + k];
    }
    __syncthreads();

    unsigned long long acc[4];
    const unsigned long long bb = dup2(b0[t]);
#pragma unroll
    for (int rp = 0; rp < 4; ++rp) acc[rp] = bb;

#pragma unroll 4
    for (int k = 0; k < C2_; ++k) {
        const unsigned long long wd = dup2(W0[k * H_ + t]);
#pragma unroll
        for (int rp = 0; rp < 4; ++rp) {
            const unsigned long long a =
                *(const unsigned long long*)&s_f[k * 10 + 2 * rp];
            acc[rp] = ffma2(a, wd, acc[rp]);
        }
    }
#pragma unroll
    for (int rp = 0; rp < 4; ++rp) {
        const float2 v = u2f(acc[rp]);
        g_P[(size_t)(base + 2 * rp) * H_ + t]     = v.x;
        g_P[(size_t)(base + 2 * rp + 1) * H_ + t] = v.y;
    }
}

// ---------------------------------------------------------------------------
// Kernel 3: fused GEMM1-finish + GEMM2 + relu + maxpool.
// 128 threads = 4 warps; each warp handles TWO query points (16 rows per
// weight load). Inner loop per k per warp: 4 LDS.128 + 4 LDG + 4 dup +
// 32 FFMA2 -> 44 inst per 64 FMA-pipe cycles (FMA-bound by design).
// ---------------------------------------------------------------------------
__global__ __launch_bounds__(128) void fused_kernel(
    const float* __restrict__ xyz1,
    const float* __restrict__ xyz2,
    const float* __restrict__ W0,
    const float* __restrict__ W1,
    const float* __restrict__ b1) {
    __shared__ unsigned long long h_s[8][H_][4];  // [point][k][row-pair]

    const int w     = threadIdx.x >> 5;
    const int lane  = threadIdx.x & 31;
    const int gbase = blockIdx.x * 8 + w * 2;
    const int rp    = lane & 3;   // row-pair (rows 2rp, 2rp+1)
    const int cg    = lane >> 2;  // col group, cols cg + 8*i

    // ---- finish GEMM1 for both points ----
#pragma unroll
    for (int pt = 0; pt < 2; ++pt) {
        const int g = gbase + pt;
        const int b = g >> 13;  // N1 = 8192
        const int j0 = g_knn[(size_t)g * K_ + 2 * rp];
        const int j1 = g_knn[(size_t)g * K_ + 2 * rp + 1];
        const float qx = xyz1[(size_t)g * 3 + 0];
        const float qy = xyz1[(size_t)g * 3 + 1];
        const float qz = xyz1[(size_t)g * 3 + 2];
        const float* p0 = xyz2 + (size_t)(b * N2_ + j0) * 3;
        const float* p1 = xyz2 + (size_t)(b * N2_ + j1) * 3;
        const float d00 = p0[0] - qx, d01 = p0[1] - qy, d02 = p0[2] - qz;
        const float d10 = p1[0] - qx, d11 = p1[1] - qy, d12 = p1[2] - qz;
        const float* P0 = g_P + (size_t)(b * N2_ + j0) * H_;
        const float* P1 = g_P + (size_t)(b * N2_ + j1) * H_;
#pragma unroll
        for (int i = 0; i < 16; ++i) {
            const int c = cg + 8 * i;
            const float v0 = W0[128 * H_ + c];
            const float v1 = W0[129 * H_ + c];
            const float v2 = W0[130 * H_ + c];
            float h0 = __ldcs(P0 + c);
            float h1 = __ldcs(P1 + c);
            h0 = fmaf(d02, v2, fmaf(d01, v1, fmaf(d00, v0, h0)));
            h1 = fmaf(d12, v2, fmaf(d11, v1, fmaf(d10, v0, h1)));
            h_s[w * 2 + pt][c][rp] = pack2(fmaxf(h0, 0.0f), fmaxf(h1, 0.0f));
        }
    }
    __syncwarp();

    // ---- GEMM2: two (8 x 128) @ (128 x 128) per warp ----
    unsigned long long acc[2][4][4];  // [point][row-pair][col i]
#pragma unroll
    for (int i = 0; i < 4; ++i) {
        const unsigned long long bb = dup2(b1[lane + 32 * i]);
#pragma unroll
        for (int r = 0; r < 4; ++r) { acc[0][r][i] = bb; acc[1][r][i] = bb; }
    }

#pragma unroll 2
    for (int k = 0; k < H_; ++k) {
        const ulonglong2 a01 = *(const ulonglong2*)&h_s[2 * w][k][0];
        const ulonglong2 a23 = *(const ulonglong2*)&h_s[2 * w][k][2];
        const ulonglong2 c01 = *(const ulonglong2*)&h_s[2 * w + 1][k][0];
        const ulonglong2 c23 = *(const ulonglong2*)&h_s[2 * w + 1][k][2];
        const unsigned long long hvA[4] = {a01.x, a01.y, a23.x, a23.y};
        const unsigned long long hvB[4] = {c01.x, c01.y, c23.x, c23.y};
#pragma unroll
        for (int i = 0; i < 4; ++i) {
            const unsigned long long wd = dup2(W1[k * H_ + lane + 32 * i]);
#pragma unroll
            for (int r = 0; r < 4; ++r) {
                acc[0][r][i] = ffma2(hvA[r], wd, acc[0][r][i]);
                acc[1][r][i] = ffma2(hvB[r], wd, acc[1][r][i]);
            }
        }
    }

    // ---- relu + maxpool over 8 neighbors -> g_pool ----
#pragma unroll
    for (int pt = 0; pt < 2; ++pt) {
        float* poolg = g_pool + (size_t)(gbase + pt) * H_;
#pragma unroll
        for (int i = 0; i < 4; ++i) {
            float m = 0.0f;  // max_r relu(x) == max(0, max_r x)
#pragma unroll
            for (int r = 0; r < 4; ++r) {
                const float2 v = u2f(acc[pt][r][i]);
                m = fmaxf(m, fmaxf(v.x, v.y));
            }
            poolg[lane + 32 * i] = m;
        }
    }
}

// ---------------------------------------------------------------------------
// Kernel 4: GEMM3  out = relu([pooled | feat1] @ W2 + b2).
// 128 threads, 32 points/block, 8 points per thread (4 row-pairs x 4 cols).
// Inner loop per k: 2 LDS.128 + 4 LDG + 4 dup + 16 FFMA2 (FMA-bound).
// smem row stride 36 floats: LDS.128-aligned, >=4-way-spread banks.
// ---------------------------------------------------------------------------
__global__ __launch_bounds__(128) void gemm3_kernel(
    const float* __restrict__ feat1,
    const float* __restrict__ W2,
    const float* __restrict__ b2,
    float* __restrict__ out) {
    __shared__ float cat_s[CAT_ * 36];  // [k][36]: 32 points + pad

    const int t = threadIdx.x;
    const int base = blockIdx.x * 32;

    // pooled channels (coalesced reads, transposed smem store)
    for (int idx = t; idx < 32 * H_; idx += 128) {
        const int p = idx >> 7, k = idx & 127;
        cat_s[k * 36 + p] = __ldcs(&g_pool[(size_t)(base + p) * H_ + k]);
    }
    // feat1 channels
    for (int idx = t; idx < 32 * C1_; idx += 128) {
        const int p = idx >> 6, k = idx & 63;
        cat_s[(H_ + k) * 36 + p] = __ldcs(&feat1[(size_t)(base + p) * C1_ + k]);
    }
    __syncthreads();

    const int q  = t & 3;   // point octet: points 8q .. 8q+7
    const int cg = t >> 2;  // cols cg + 32*i

    unsigned long long acc[4][4];  // [row-pair][col i]
#pragma unroll
    for (int i = 0; i < 4; ++i) {
        const unsigned long long bb = dup2(b2[cg + 32 * i]);
#pragma unroll
        for (int r = 0; r < 4; ++r) acc[r][i] = bb;
    }

#pragma unroll 2
    for (int k = 0; k < CAT_; ++k) {
        const ulonglong2 a01 = *(const ulonglong2*)&cat_s[k * 36 + 8 * q];
        const ulonglong2 a23 = *(const ulonglong2*)&cat_s[k * 36 + 8 * q + 4];
        const unsigned long long hv[4] = {a01.x, a01.y, a23.x, a23.y};
#pragma unroll
        for (int i = 0; i < 4; ++i) {
            const unsigned long long wd = dup2(W2[k * H_ + cg + 32 * i]);
#pragma unroll
            for (int r = 0; r < 4; ++r) acc[r][i] = ffma2(hv[r], wd, acc[r][i]);
        }
    }

#pragma unroll
    for (int r = 0; r < 4; ++r) {
#pragma unroll
        for (int i = 0; i < 4; ++i) {
            const float2 v = u2f(acc[r][i]);
            const int c = cg + 32 * i;
            out[(size_t)(base + 8 * q + 2 * r)     * H_ + c] = fmaxf(v.x, 0.0f);
            out[(size_t)(base + 8 * q + 2 * r + 1) * H_ + c] = fmaxf(v.y, 0.0f);
        }
    }
}

// ---------------------------------------------------------------------------
// Launch
// ---------------------------------------------------------------------------
extern "C" void kernel_launch(void* const* d_in, const int* in_sizes, int n_in,
                              void* d_out, int out_size) {
    const float* xyz1  = (const float*)d_in[0];
    const float* xyz2  = (const float*)d_in[1];
    const float* feat1 = (const float*)d_in[2];
    const float* feat2 = (const float*)d_in[3];
    const float* W0    = (const float*)d_in[4];
    const float* b0    = (const float*)d_in[5];
    const float* W1    = (const float*)d_in[6];
    const float* b1    = (const float*)d_in[7];
    const float* W2    = (const float*)d_in[8];
    const float* b2    = (const float*)d_in[9];
    float* out = (float*)d_out;

    precompute_p_kernel<<<(B_ * N2_) / 8, 128>>>(feat2, W0, b0);
    knn_kernel<<<dim3(N1_ / 256, B_), 256>>>(xyz1, xyz2);
    fused_kernel<<<(B_ * N1_) / 8, 128>>>(xyz1, xyz2, W0, W1, b1);
    gemm3_kernel<<<(B_ * N1_) / 32, 128>>>(feat1, W2, b2, out);
}